// round 2
// baseline (speedup 1.0000x reference)
#include <cuda_runtime.h>
#include <math.h>

#define BB 4
#define LL 8192
#define DD 2048
#define BLT (BB * LL)          // 32768 rows
#define CAP (LL / 2)           // capacity = 4096
#define NBLK (BLT / 8)         // 4096 matvec blocks
#define NOISE_SCALE 0.1f
#define AUX_W 0.01f
#define CAP_F 0.5f

// Scratch (allocations forbidden): order-mapped noisy keys + per-block sigmoid partials.
__device__ unsigned g_keys[BLT];
__device__ float    g_part[NBLK];

// ---------------------------------------------------------------------------
// Kernel 1: router matvec. 1 warp/row, 8 rows per 256-thread block.
//   out[BLT + row] = clean logit
//   g_keys[row]    = noisy logit mapped to order-preserving unsigned
//   g_part[blk]    = sum of sigmoid(clean logit) over the block's 8 rows
// ---------------------------------------------------------------------------
__global__ __launch_bounds__(256) void matvec_kernel(
    const float* __restrict__ x,
    const float* __restrict__ noise,
    const float* __restrict__ w,
    float* __restrict__ out)
{
    __shared__ float4 sw[DD / 4];     // 8 KB
    __shared__ float  ssig[8];

    const int t = threadIdx.x;
    const float4* w4 = reinterpret_cast<const float4*>(w);
    sw[t]       = w4[t];
    sw[t + 256] = w4[t + 256];
    __syncthreads();

    const int warp = t >> 5;
    const int lane = t & 31;
    const int row  = blockIdx.x * 8 + warp;

    const float4* xr = reinterpret_cast<const float4*>(x + (size_t)row * DD);
    float acc = 0.0f;
#pragma unroll
    for (int j = 0; j < 16; j++) {
        const float4 xv = __ldg(&xr[lane + 32 * j]);
        const float4 wv = sw[lane + 32 * j];
        acc = fmaf(xv.x, wv.x, acc);
        acc = fmaf(xv.y, wv.y, acc);
        acc = fmaf(xv.z, wv.z, acc);
        acc = fmaf(xv.w, wv.w, acc);
    }
#pragma unroll
    for (int o = 16; o; o >>= 1) acc += __shfl_down_sync(0xffffffffu, acc, o);

    if (lane == 0) {
        out[BLT + row] = acc;                                   // clean logit
        const float ny = fmaf(noise[row], NOISE_SCALE, acc);    // noisy logit
        const unsigned b = __float_as_uint(ny);
        g_keys[row] = b ^ (((int)b >> 31) | 0x80000000u);       // monotone map
        ssig[warp]  = 1.0f / (1.0f + expf(-acc));
    }
    __syncthreads();
    if (t == 0) {
        float s = 0.0f;
#pragma unroll
        for (int i = 0; i < 8; i++) s += ssig[i];
        g_part[blockIdx.x] = s;    // plain store — no zeroing kernel needed
    }
}

// ---------------------------------------------------------------------------
// Kernel 2: blocks 0..3 = per-row exact top-CAP mask (byte-radix select),
//           block 4     = aux loss reduction over g_part.
// ---------------------------------------------------------------------------
__global__ __launch_bounds__(1024) void select_aux_kernel(float* __restrict__ out)
{
    const int t = threadIdx.x;

    // ---------------- aux block ----------------
    if (blockIdx.x == BB) {
        __shared__ double s_sum[BB];
        if (t < BB) s_sum[t] = 0.0;
        __syncthreads();
        // batch b owns g_part[b*1024 .. b*1024+1023]; thread t takes one per batch
        double v[BB];
#pragma unroll
        for (int b = 0; b < BB; b++) v[b] = (double)g_part[b * (NBLK / BB) + t];
#pragma unroll
        for (int o = 16; o; o >>= 1)
#pragma unroll
            for (int b = 0; b < BB; b++)
                v[b] += __shfl_down_sync(0xffffffffu, v[b], o);
        if ((t & 31) == 0)
#pragma unroll
            for (int b = 0; b < BB; b++) atomicAdd(&s_sum[b], v[b]);
        __syncthreads();
        if (t == 0) {
            double a = 0.0;
#pragma unroll
            for (int b = 0; b < BB; b++) {
                const double d = s_sum[b] / (double)LL - (double)CAP_F;
                a += d * d;
            }
            out[2 * BLT] = (float)((double)AUX_W * a / (double)BB);
        }
        return;
    }

    // ---------------- select blocks ----------------
    __shared__ unsigned s_hist[256];
    __shared__ unsigned s_state[2];   // [0]=prefix, [1]=need
    __shared__ unsigned s_cnt;
    __shared__ int      s_eqn;
    __shared__ int      s_eqi[256];

    const int row = blockIdx.x;
    const int EPT = LL / 1024;        // 8 keys per thread

    unsigned k[8];
#pragma unroll
    for (int j = 0; j < EPT; j++) k[j] = g_keys[row * LL + t * EPT + j];

    if (t == 0) { s_state[0] = 0u; s_state[1] = CAP; s_eqn = 0; s_cnt = 0u; }

    // 4-pass byte radix: find exact CAP-th largest key value
#pragma unroll
    for (int pass = 0; pass < 4; pass++) {
        const int s = 24 - 8 * pass;
        if (t < 256) s_hist[t] = 0u;
        __syncthreads();
        const unsigned prefix = s_state[0];
#pragma unroll
        for (int j = 0; j < EPT; j++) {
            bool in = (pass == 0) || (((k[j] ^ prefix) >> (s + 8)) == 0u);
            if (in) atomicAdd(&s_hist[(k[j] >> s) & 255u], 1u);
        }
        __syncthreads();
        if (t == 0) {
            unsigned need = s_state[1], cum = 0u;
            int bin = 0;
            for (int i = 255; i >= 0; i--) {
                const unsigned h = s_hist[i];
                if (cum + h >= need) { bin = i; need -= cum; break; }
                cum += h;
            }
            s_state[0] = prefix | ((unsigned)bin << s);
            s_state[1] = need;
        }
        __syncthreads();
    }
    const unsigned thr = s_state[0];  // exact CAP-th largest key

    // count strictly-greater; collect tie indices
    int cg = 0;
#pragma unroll
    for (int j = 0; j < EPT; j++) cg += (k[j] > thr);
    cg = __reduce_add_sync(0xffffffffu, cg);
    if ((t & 31) == 0 && cg) atomicAdd(&s_cnt, (unsigned)cg);
#pragma unroll
    for (int j = 0; j < EPT; j++) {
        if (k[j] == thr) {
            const int p = atomicAdd(&s_eqn, 1);
            if (p < 256) s_eqi[p] = t * EPT + j;
        }
    }

    // write strict-greater mask
    float* m = out + row * LL;
#pragma unroll
    for (int j = 0; j < EPT; j++)
        m[t * EPT + j] = (k[j] > thr) ? 1.0f : 0.0f;
    __syncthreads();

    // promote lowest-index ties to fill exactly CAP slots (top_k order)
    if (t == 0) {
        int need = CAP - (int)s_cnt;
        const int n = (s_eqn < 256) ? s_eqn : 256;
        for (int sel = 0; sel < need; sel++) {
            int best = 0x7fffffff, bi = -1;
            for (int q = 0; q < n; q++)
                if (s_eqi[q] >= 0 && s_eqi[q] < best) { best = s_eqi[q]; bi = q; }
            if (bi < 0) break;
            m[best]   = 1.0f;
            s_eqi[bi] = -1;
        }
    }
}

// ---------------------------------------------------------------------------
extern "C" void kernel_launch(void* const* d_in, const int* in_sizes, int n_in,
                              void* d_out, int out_size)
{
    const float* x     = (const float*)d_in[0];
    const float* noise = (const float*)d_in[1];
    const float* w     = (const float*)d_in[2];
    float* out = (float*)d_out;      // [mask BL | logits BL | aux 1]
    (void)in_sizes; (void)n_in; (void)out_size;

    matvec_kernel<<<NBLK, 256>>>(x, noise, w, out);
    select_aux_kernel<<<BB + 1, 1024>>>(out);
}

// round 3
// speedup vs baseline: 1.1496x; 1.1496x over previous
#include <cuda_runtime.h>
#include <math.h>

#define BB 4
#define LL 8192
#define DD 2048
#define BLT (BB * LL)          // 32768 rows
#define CAP (LL / 2)           // 4096
#define NOISE_SCALE 0.1f
#define AUX_W 0.01f
#define CAP_F 0.5f

#define GRID 256
#define TPB  512
#define RPB  (BLT / GRID)      // 128 rows per block
#define RPW  (RPB / (TPB/32))  // 8 rows per warp
#define EPT  (LL / TPB)        // 16 keys per thread (select phase)

// Scratch (allocations forbidden)
__device__ unsigned g_keys[BLT];
__device__ float    g_part[GRID];
__device__ unsigned g_bar     = 0;   // reset to 0 by last arriver each launch
__device__ unsigned g_release = 0;   // monotonically increments once per launch

__global__ __launch_bounds__(TPB, 2) void fused_kernel(
    const float* __restrict__ x,
    const float* __restrict__ noise,
    const float* __restrict__ w,
    float* __restrict__ out)
{
    __shared__ float4   sw[DD / 4];      // 8 KB: router weight
    __shared__ float    s_ws[16];
    __shared__ unsigned s_hist[256];
    __shared__ unsigned s_tot[8];
    __shared__ unsigned s_state[2];      // [0]=prefix, [1]=need
    __shared__ unsigned s_cnt;
    __shared__ int      s_eqn;
    __shared__ int      s_eqi[256];
    __shared__ double   s_db[BB];

    const int t    = threadIdx.x;
    const int warp = t >> 5;
    const int lane = t & 31;
    const int bid  = blockIdx.x;

    // ---------------- phase 1: matvec (all 256 blocks) ----------------
    const float4* w4 = reinterpret_cast<const float4*>(w);
    sw[t] = w4[t];                       // 512 threads, 512 float4
    __syncthreads();

    float ssum = 0.0f;
#pragma unroll
    for (int r = 0; r < RPW; r++) {
        const int row = bid * RPB + warp * RPW + r;
        const float4* xr = reinterpret_cast<const float4*>(x + (size_t)row * DD);
        float acc = 0.0f;
#pragma unroll
        for (int j = 0; j < 16; j++) {
            const float4 xv = __ldg(&xr[lane + 32 * j]);
            const float4 wv = sw[lane + 32 * j];
            acc = fmaf(xv.x, wv.x, acc);
            acc = fmaf(xv.y, wv.y, acc);
            acc = fmaf(xv.z, wv.z, acc);
            acc = fmaf(xv.w, wv.w, acc);
        }
#pragma unroll
        for (int o = 16; o; o >>= 1) acc += __shfl_down_sync(0xffffffffu, acc, o);
        if (lane == 0) {
            out[BLT + row] = acc;                                // clean logit
            const float ny = fmaf(noise[row], NOISE_SCALE, acc); // noisy logit
            const unsigned b = __float_as_uint(ny);
            g_keys[row] = b ^ (((int)b >> 31) | 0x80000000u);    // monotone map
            ssum += 1.0f / (1.0f + expf(-acc));
        }
    }
    if (lane == 0) s_ws[warp] = ssum;
    __syncthreads();
    if (t == 0) {
        float s = 0.0f;
#pragma unroll
        for (int i = 0; i < 16; i++) s += s_ws[i];
        g_part[bid] = s;     // plain store, no init needed
    }

    // ---------------- device-wide barrier (single wave guaranteed) ------
    __threadfence();          // publish this thread's writes device-wide
    __syncthreads();
    unsigned start = 0;
    if (t == 0) {
        start = *(volatile unsigned*)&g_release;   // read BEFORE arrival
        const unsigned tk = atomicAdd(&g_bar, 1u);
        if (tk == GRID - 1) {                      // last arriver
            g_bar = 0u;                            // reset for next replay
            __threadfence();
            atomicAdd(&g_release, 1u);             // release
        }
    }
    if (bid >= BB + 1) return;                     // blocks 5..255 done
    if (t == 0) {
        while (*(volatile unsigned*)&g_release == start) __nanosleep(64);
        __threadfence();
    }
    __syncthreads();

    // ---------------- phase 2a: aux loss (block 4) ----------------------
    if (bid == BB) {
        if (t < 32 * BB) {                         // warp b owns batch b (64 partials)
            const int wb = warp;
            double v = (double)g_part[wb * 64 + lane]
                     + (double)g_part[wb * 64 + 32 + lane];
#pragma unroll
            for (int o = 16; o; o >>= 1) v += __shfl_down_sync(0xffffffffu, v, o);
            if (lane == 0) s_db[wb] = v;
        }
        __syncthreads();
        if (t == 0) {
            double a = 0.0;
#pragma unroll
            for (int b = 0; b < BB; b++) {
                const double d = s_db[b] / (double)LL - (double)CAP_F;
                a += d * d;
            }
            out[2 * BLT] = (float)((double)AUX_W * a / (double)BB);
        }
        return;
    }

    // ---------------- phase 2b: per-row top-CAP select (blocks 0..3) ----
    const int row = bid;
    unsigned k[EPT];
    {
        const uint4* kr = reinterpret_cast<const uint4*>(g_keys + row * LL);
#pragma unroll
        for (int q = 0; q < EPT / 4; q++) {
            const uint4 v = kr[t * (EPT / 4) + q];
            k[q * 4 + 0] = v.x; k[q * 4 + 1] = v.y;
            k[q * 4 + 2] = v.z; k[q * 4 + 3] = v.w;
        }
    }
    if (t == 0) { s_state[0] = 0u; s_state[1] = CAP; s_cnt = 0u; s_eqn = 0; }

    // 4-pass byte radix with cooperative suffix-scan bin selection
#pragma unroll
    for (int pass = 0; pass < 4; pass++) {
        const int s  = 24 - 8 * pass;
        const int hs = (pass == 0) ? 0 : (s + 8);
        if (t < 256) s_hist[t] = 0u;
        __syncthreads();
        const unsigned prefix = s_state[0];
        const unsigned need   = s_state[1];
#pragma unroll
        for (int j = 0; j < EPT; j++) {
            if (pass == 0 || (((k[j] ^ prefix) >> hs) == 0u))
                atomicAdd(&s_hist[(k[j] >> s) & 255u], 1u);
        }
        __syncthreads();
        // suffix sums over 256 bins: 8 warps (threads 0..255)
        unsigned h = 0, v = 0;
        if (t < 256) { h = s_hist[t]; v = h; }
#pragma unroll
        for (int o = 1; o < 32; o <<= 1) {
            const unsigned u = __shfl_down_sync(0xffffffffu, v, o);
            if (lane + o < 32) v += u;
        }
        if (t < 256 && lane == 0) s_tot[warp] = v;
        __syncthreads();
        if (t < 256) {
            unsigned carry = 0;
            for (int w2 = warp + 1; w2 < 8; w2++) carry += s_tot[w2];
            const unsigned S = v + carry;            // suffix sum incl. own bin
            if (h > 0u && S >= need && (S - h) < need) {
                s_state[0] = prefix | ((unsigned)t << s);
                s_state[1] = need - (S - h);
            }
        }
        __syncthreads();
    }
    const unsigned thr = s_state[0];                 // exact CAP-th largest key

    // strictly-greater count + tie index collection
    int cg = 0;
#pragma unroll
    for (int j = 0; j < EPT; j++) cg += (k[j] > thr);
    cg = __reduce_add_sync(0xffffffffu, cg);
    if (lane == 0 && cg) atomicAdd(&s_cnt, (unsigned)cg);
#pragma unroll
    for (int j = 0; j < EPT; j++) {
        if (k[j] == thr) {
            const int p = atomicAdd(&s_eqn, 1);
            if (p < 256) s_eqi[p] = t * EPT + j;
        }
    }

    // strict-greater mask write
    float* m = out + row * LL;
#pragma unroll
    for (int j = 0; j < EPT; j++)
        m[t * EPT + j] = (k[j] > thr) ? 1.0f : 0.0f;
    __syncthreads();

    // promote lowest-index ties to fill exactly CAP (jax top_k order)
    if (t == 0) {
        int need = CAP - (int)s_cnt;
        const int n = (s_eqn < 256) ? s_eqn : 256;
        for (int sel = 0; sel < need; sel++) {
            int best = 0x7fffffff, bi = -1;
            for (int q = 0; q < n; q++)
                if (s_eqi[q] >= 0 && s_eqi[q] < best) { best = s_eqi[q]; bi = q; }
            if (bi < 0) break;
            m[best]   = 1.0f;
            s_eqi[bi] = -1;
        }
    }
}

// ---------------------------------------------------------------------------
extern "C" void kernel_launch(void* const* d_in, const int* in_sizes, int n_in,
                              void* d_out, int out_size)
{
    const float* x     = (const float*)d_in[0];
    const float* noise = (const float*)d_in[1];
    const float* w     = (const float*)d_in[2];
    float* out = (float*)d_out;   // [mask BL | logits BL | aux 1]
    (void)in_sizes; (void)n_in; (void)out_size;

    fused_kernel<<<GRID, TPB>>>(x, noise, w, out);
}